// round 11
// baseline (speedup 1.0000x reference)
#include <cuda_runtime.h>
#include <cstdint>

#define KK 4096
#define NPIX (64*32*256)
#define POSINF __int_as_float(0x7f800000)
#define OFF1 64
#define OFF2 320
#define OFF3 1344
#define OFF4 5440

__device__ float g_zrest[NPIX];
__device__ float g_zflat[22016*32];
__device__ float g_zsq[22016];
__device__ float g_wsq[KK];
__device__ float g_pd[32768];
__device__ int   g_pi[32768];

typedef unsigned long long ull;

// ---------- cubic (jax Keys a=-0.5) weights, renormalized ----------
template<int PN>
__device__ __forceinline__ void cubw(int o, float* w) {
    if (PN == 1) { w[0] = 1.f; return; }
    float s = __fadd_rn(__fmul_rn(__fadd_rn((float)o, 0.5f), (float)PN / 16.f), -0.5f);
    float tot = 0.f;
#pragma unroll
    for (int i = 0; i < PN; i++) {
        float x = fabsf(s - (float)i);
        float v;
        if (x >= 2.f)      v = 0.f;
        else if (x >= 1.f) v = ((-0.5f * x + 2.5f) * x - 4.f) * x + 2.f;
        else               v = ((1.5f * x - 2.5f) * x) * x + 1.f;
        w[i] = v; tot += v;
    }
#pragma unroll
    for (int i = 0; i < PN; i++) w[i] = w[i] / tot;
}

// ---------- shared up-phase: gather + bicubic + zrest + next-level prep -----
// reads tok_s[NT] (smem), zrestSrc; writes outCur, g_zrest, zflat/zsq @wOff.
template<int PN, int PNN>
__device__ void up_phase(int b, const int* tok_s, const float* __restrict__ emb,
                         const float* __restrict__ outPrev, float* __restrict__ outCur,
                         int isFirst, int wOff, const float* __restrict__ zrestSrc) {
    constexpr int NT = PN * PN;
    constexpr int SUB = 16 / PNN;
    __shared__ float ew[NT][33];
    __shared__ float zt[32][256];
    int tid = threadIdx.x;

    for (int idx = tid; idx < NT * 8; idx += 256) {
        int token = idx >> 3, seg = idx & 7;
        float4 v = *(const float4*)(emb + tok_s[token] * 32 + seg * 4);
        ew[token][seg*4+0] = v.x; ew[token][seg*4+1] = v.y;
        ew[token][seg*4+2] = v.z; ew[token][seg*4+3] = v.w;
    }
    __syncthreads();

    int y = tid >> 4, x = tid & 15;
    float wy[PN], wx[PN];
    cubw<PN>(y, wy);
    cubw<PN>(x, wx);
#pragma unroll
    for (int c = 0; c < 32; c++) {
        float acc = 0.f;
#pragma unroll
        for (int j = 0; j < PN; j++) {
            float tmp = 0.f;
#pragma unroll
            for (int i = 0; i < PN; i++) tmp += wx[i] * ew[j * PN + i][c];
            acc += wy[j] * tmp;
        }
        int idx = (b * 32 + c) * 256 + y * 16 + x;
        float prev = isFirst ? 0.f : outPrev[idx];
        outCur[idx] = prev + acc;
        float nz = zrestSrc[idx] - acc;
        g_zrest[idx] = nz;
        zt[c][tid] = nz;
    }
    __syncthreads();

    if (tid < PNN * PNN) {
        int ty2 = tid / PNN, tx2 = tid % PNN;
        float buf[32];
        float zqacc = 0.f;
#pragma unroll
        for (int c = 0; c < 32; c++) {
            float s = 0.f;
            for (int dy = 0; dy < SUB; dy++)
                for (int dx = 0; dx < SUB; dx++)
                    s = __fadd_rn(s, zt[c][(ty2 * SUB + dy) * 16 + tx2 * SUB + dx]);
            float zd = __fmul_rn(s, 1.f / (float)(SUB * SUB));
            buf[c] = zd;
            zqacc = __fadd_rn(zqacc, __fmul_rn(zd, zd));
        }
        int row = wOff + b * PNN * PNN + tid;
        float* dst = g_zflat + (size_t)row * 32;
#pragma unroll
        for (int s8 = 0; s8 < 8; s8++)
            *(float4*)(dst + s8 * 4) = make_float4(buf[s8*4], buf[s8*4+1],
                                                   buf[s8*4+2], buf[s8*4+3]);
        g_zsq[row] = zqacc;
    }
}

// ---------- level 0: wsq + downsample + dist + up + L1 prep (fully fused) ---
__global__ void __launch_bounds__(256) k_lvl0(const float* __restrict__ z,
                                              const float* __restrict__ emb,
                                              float* __restrict__ out0) {
    __shared__ float zds[32];
    __shared__ float zqs;
    __shared__ float pdw[8];
    __shared__ int   piw[8];
    __shared__ int   tok_s[1];
    int b = blockIdx.x, tid = threadIdx.x;
    int wid = tid >> 5, lane = tid & 31;

    if (tid < 32) {
        const float* base = z + (b * 32 + tid) * 256;
        float s = 0.f;
        for (int i = 0; i < 256; i++) s = __fadd_rn(s, base[i]);
        float zd = __fmul_rn(s, 1.f / 256.f);
        zds[tid] = zd;
        float q = __fmul_rn(zd, zd);
#pragma unroll
        for (int off = 16; off; off >>= 1)
            q = __fadd_rn(q, __shfl_xor_sync(0xffffffffu, q, off));
        if (tid == 0) zqs = q;
    }
    __syncthreads();

    float zr[32];
#pragma unroll
    for (int c = 0; c < 32; c++) zr[c] = zds[c];
    float zq = zqs;

    float bd = POSINF; int bk = 0;
    for (int kk = 0; kk < 16; kk++) {
        int k = tid * 16 + kk;
        const float4* e4 = (const float4*)(emb + k * 32);
        float ws = 0.f, dot = 0.f;
#pragma unroll
        for (int s8 = 0; s8 < 8; s8++) {
            float4 w4 = e4[s8];
            ws = __fadd_rn(ws, __fmul_rn(w4.x, w4.x)); dot = __fmaf_rn(zr[s8*4+0], w4.x, dot);
            ws = __fadd_rn(ws, __fmul_rn(w4.y, w4.y)); dot = __fmaf_rn(zr[s8*4+1], w4.y, dot);
            ws = __fadd_rn(ws, __fmul_rn(w4.z, w4.z)); dot = __fmaf_rn(zr[s8*4+2], w4.z, dot);
            ws = __fadd_rn(ws, __fmul_rn(w4.w, w4.w)); dot = __fmaf_rn(zr[s8*4+3], w4.w, dot);
        }
        g_wsq[k] = ws;
        float d = __fadd_rn(__fadd_rn(zq, ws), __fmul_rn(-2.f, dot));
        if (d < bd) { bd = d; bk = k; }
    }
#pragma unroll
    for (int off = 16; off; off >>= 1) {
        float od = __shfl_xor_sync(0xffffffffu, bd, off);
        int   ok = __shfl_xor_sync(0xffffffffu, bk, off);
        if (od < bd || (od == bd && ok < bk)) { bd = od; bk = ok; }
    }
    if (lane == 0) { pdw[wid] = bd; piw[wid] = bk; }
    __syncthreads();
    if (tid == 0) {
        float bdv = pdw[0]; int bkv = piw[0];
        for (int wd = 1; wd < 8; wd++)
            if (pdw[wd] < bdv || (pdw[wd] == bdv && piw[wd] < bkv)) { bdv = pdw[wd]; bkv = piw[wd]; }
        tok_s[0] = bkv;
    }
    __syncthreads();

    up_phase<1, 2>(b, tok_s, emb, out0, out0, 1, OFF1, z);
}

// ---------- level 1: dist (4 tokens) + up + L2 prep (fully fused) ----------
__global__ void __launch_bounds__(256) k_lvl1(const float* __restrict__ emb,
                                              const float* __restrict__ out0,
                                              float* __restrict__ out1) {
    __shared__ float zsm[4][32];
    __shared__ float zqsm[4];
    __shared__ float pdw[8][4];
    __shared__ int   piw[8][4];
    __shared__ int   tok_s[4];
    int b = blockIdx.x, tid = threadIdx.x;
    int wid = tid >> 5, lane = tid & 31;

    if (tid < 128)
        zsm[tid >> 5][tid & 31] = g_zflat[(size_t)(OFF1 + b * 4 + (tid >> 5)) * 32 + (tid & 31)];
    if (tid < 4) zqsm[tid] = g_zsq[OFF1 + b * 4 + tid];
    __syncthreads();

    int t = tid & 3, g = tid >> 2;     // 64 code groups x 4 tokens
    float zr[32];
#pragma unroll
    for (int c = 0; c < 32; c++) zr[c] = zsm[t][c];
    float zq = zqsm[t];

    float bd = POSINF; int bk = 0;
    for (int kk = 0; kk < 64; kk++) {
        int k = g * 64 + kk;
        const float4* e4 = (const float4*)(emb + k * 32);
        float dot = 0.f;
#pragma unroll
        for (int s8 = 0; s8 < 8; s8++) {
            float4 w4 = e4[s8];
            dot = __fmaf_rn(zr[s8*4+0], w4.x, dot);
            dot = __fmaf_rn(zr[s8*4+1], w4.y, dot);
            dot = __fmaf_rn(zr[s8*4+2], w4.z, dot);
            dot = __fmaf_rn(zr[s8*4+3], w4.w, dot);
        }
        float d = __fadd_rn(__fadd_rn(zq, g_wsq[k]), __fmul_rn(-2.f, dot));
        if (d < bd) { bd = d; bk = k; }
    }
#pragma unroll
    for (int off = 4; off <= 16; off <<= 1) {
        float od = __shfl_xor_sync(0xffffffffu, bd, off);
        int   ok = __shfl_xor_sync(0xffffffffu, bk, off);
        if (od < bd || (od == bd && ok < bk)) { bd = od; bk = ok; }
    }
    if (lane < 4) { pdw[wid][lane] = bd; piw[wid][lane] = bk; }
    __syncthreads();
    if (tid < 4) {
        float bdv = pdw[0][tid]; int bkv = piw[0][tid];
        for (int wd = 1; wd < 8; wd++)
            if (pdw[wd][tid] < bdv || (pdw[wd][tid] == bdv && piw[wd][tid] < bkv))
                { bdv = pdw[wd][tid]; bkv = piw[wd][tid]; }
        tok_s[tid] = bkv;
    }
    __syncthreads();

    up_phase<2, 4>(b, tok_s, emb, out0, out1, 0, OFF2, g_zrest);
}

// ---------- dist+argmin (L2-L4): 64 tok x 128 codes, pipelined f32x2 --------
__global__ void __launch_bounds__(256, 2) k_dist(const float* __restrict__ emb,
                                                 int cps, int iters, int rowOff) {
    __shared__ float zs[32][64];
    __shared__ ulonglong2 es2[4][32][16];
    __shared__ float ws[128];
    int tid = threadIdx.x;
    int tx = tid & 15, ty = tid >> 4;
    int tb = blockIdx.x * 64;

    {
        int tok = tid >> 2, part = tid & 3;
        const float4* p = (const float4*)(g_zflat + (size_t)(rowOff + tb + tok) * 32 + part * 8);
        float4 a = p[0], b4 = p[1];
        int c0 = part * 8;
        zs[c0+0][tok]=a.x;  zs[c0+1][tok]=a.y;  zs[c0+2][tok]=a.z;  zs[c0+3][tok]=a.w;
        zs[c0+4][tok]=b4.x; zs[c0+5][tok]=b4.y; zs[c0+6][tok]=b4.z; zs[c0+7][tok]=b4.w;
    }
    float zq[4];
#pragma unroll
    for (int j = 0; j < 4; j++) zq[j] = g_zsq[rowOff + tb + ty * 4 + j];

    float bd[4]; int bk[4];
#pragma unroll
    for (int j = 0; j < 4; j++) { bd[j] = POSINF; bk[j] = 0; }

    int kbase = blockIdx.y * cps;
    for (int it = 0; it < iters; it++) {
        int kb = kbase + it * 128;
        __syncthreads();
        {
            int pair = tid >> 2, part = tid & 3;
            int txi = pair & 15, h = pair >> 4;
            int c0 = part * 8;
            int code0 = kb + txi * 8 + 2 * h;
            const float4* p0 = (const float4*)(emb + code0 * 32 + part * 8);
            const float4* p1 = (const float4*)(emb + (code0 + 1) * 32 + part * 8);
            float4 a0 = p0[0], a1 = p0[1];
            float4 b0 = p1[0], b1 = p1[1];
            float e0[8] = {a0.x,a0.y,a0.z,a0.w,a1.x,a1.y,a1.z,a1.w};
            float e1[8] = {b0.x,b0.y,b0.z,b0.w,b1.x,b1.y,b1.z,b1.w};
#pragma unroll
            for (int i = 0; i < 8; i++) {
                ull d0, d1;
                asm("mov.b64 %0, {%1, %1};" : "=l"(d0) : "f"(e0[i]));
                asm("mov.b64 %0, {%1, %1};" : "=l"(d1) : "f"(e1[i]));
                es2[h][c0 + i][txi] = make_ulonglong2(d0, d1);
            }
        }
        if (tid < 128) ws[tid] = g_wsq[kb + tid];
        __syncthreads();

        ull acc[2][8];
#pragma unroll
        for (int p = 0; p < 2; p++)
#pragma unroll
            for (int k = 0; k < 8; k++) acc[p][k] = 0ull;

        // software-pipelined mainloop: prefetch c+1 operands before c's FMAs
        ull zp[2], ed[8];
        {
            ulonglong2 zp2 = *(const ulonglong2*)&zs[0][ty * 4];
            zp[0] = zp2.x; zp[1] = zp2.y;
            ulonglong2 e0 = es2[0][0][tx], e1 = es2[1][0][tx];
            ulonglong2 e2 = es2[2][0][tx], e3 = es2[3][0][tx];
            ed[0]=e0.x; ed[1]=e0.y; ed[2]=e1.x; ed[3]=e1.y;
            ed[4]=e2.x; ed[5]=e2.y; ed[6]=e3.x; ed[7]=e3.y;
        }
#pragma unroll
        for (int c = 0; c < 32; c++) {
            ull zpn[2], edn[8];
            if (c < 31) {
                ulonglong2 zp2 = *(const ulonglong2*)&zs[c + 1][ty * 4];
                zpn[0] = zp2.x; zpn[1] = zp2.y;
                ulonglong2 e0 = es2[0][c + 1][tx], e1 = es2[1][c + 1][tx];
                ulonglong2 e2 = es2[2][c + 1][tx], e3 = es2[3][c + 1][tx];
                edn[0]=e0.x; edn[1]=e0.y; edn[2]=e1.x; edn[3]=e1.y;
                edn[4]=e2.x; edn[5]=e2.y; edn[6]=e3.x; edn[7]=e3.y;
            }
#pragma unroll
            for (int p = 0; p < 2; p++)
#pragma unroll
                for (int k = 0; k < 8; k++)
                    asm("fma.rn.f32x2 %0, %1, %2, %0;"
                        : "+l"(acc[p][k]) : "l"(zp[p]), "l"(ed[k]));
            if (c < 31) {
                zp[0] = zpn[0]; zp[1] = zpn[1];
#pragma unroll
                for (int i = 0; i < 8; i++) ed[i] = edn[i];
            }
        }

#pragma unroll
        for (int p = 0; p < 2; p++) {
#pragma unroll
            for (int k = 0; k < 8; k++) {
                float lo, hi;
                asm("mov.b64 {%0, %1}, %2;" : "=f"(lo), "=f"(hi) : "l"(acc[p][k]));
                int kk = kb + tx * 8 + k;
                float wv = ws[tx * 8 + k];
                float d0 = __fadd_rn(__fadd_rn(zq[2*p],   wv), __fmul_rn(-2.f, lo));
                float d1 = __fadd_rn(__fadd_rn(zq[2*p+1], wv), __fmul_rn(-2.f, hi));
                if (d0 < bd[2*p])   { bd[2*p]   = d0; bk[2*p]   = kk; }
                if (d1 < bd[2*p+1]) { bd[2*p+1] = d1; bk[2*p+1] = kk; }
            }
        }
    }

#pragma unroll
    for (int j = 0; j < 4; j++) {
        float d = bd[j]; int k = bk[j];
#pragma unroll
        for (int off = 8; off; off >>= 1) {
            float od = __shfl_xor_sync(0xffffffffu, d, off, 16);
            int   ok = __shfl_xor_sync(0xffffffffu, k, off, 16);
            if (od < d || (od == d && ok < k)) { d = od; k = ok; }
        }
        if (tx == 0) {
            int t = tb + ty * 4 + j;
            g_pd[t * gridDim.y + blockIdx.y] = d;
            g_pi[t * gridDim.y + blockIdx.y] = k;
        }
    }
}

// ---------- k_up: ksplit-reduce + up_phase (levels 2,3) ----------
template<int PN, int PNN>
__global__ void __launch_bounds__(256) k_up(const float* __restrict__ emb,
                                            const float* __restrict__ outPrev,
                                            float* __restrict__ outCur,
                                            int KS, int wOff) {
    constexpr int NT = PN * PN;
    __shared__ float pdp[512];
    __shared__ int   pip[512];
    __shared__ int   tok_s[NT];
    int b = blockIdx.x, tid = threadIdx.x;

    int tot = NT * KS;
    for (int i = tid; i < tot; i += 256) {
        pdp[i] = g_pd[b * tot + i];
        pip[i] = g_pi[b * tot + i];
    }
    __syncthreads();
    if (tid < NT) {
        float bdv = pdp[tid * KS]; int bkv = pip[tid * KS];
        for (int s = 1; s < KS; s++) {
            float d = pdp[tid * KS + s]; int k = pip[tid * KS + s];
            if (d < bdv || (d == bdv && k < bkv)) { bdv = d; bkv = k; }
        }
        tok_s[tid] = bkv;
    }
    __syncthreads();

    up_phase<PN, PNN>(b, tok_s, emb, outPrev, outCur, 0, wOff, g_zrest);
}

// ---------- last level: reduce + gather + accumulate ----------
__global__ void __launch_bounds__(256) k_up_last(const float* __restrict__ emb,
                                                 const float* __restrict__ outPrev,
                                                 float* __restrict__ outCur, int KS) {
    __shared__ float pdp[512];
    __shared__ int   pip[512];
    __shared__ int   tok_s[256];
    int b = blockIdx.x, tid = threadIdx.x;
    int tot = 256 * KS;
    for (int i = tid; i < tot; i += 256) {
        pdp[i] = g_pd[b * tot + i];
        pip[i] = g_pi[b * tot + i];
    }
    __syncthreads();
    {
        float bdv = pdp[tid * KS]; int bkv = pip[tid * KS];
        for (int s = 1; s < KS; s++) {
            float d = pdp[tid * KS + s]; int k = pip[tid * KS + s];
            if (d < bdv || (d == bdv && k < bkv)) { bdv = d; bkv = k; }
        }
        tok_s[tid] = bkv;
    }
    __syncthreads();
    const float* e = emb + tok_s[tid] * 32;
#pragma unroll
    for (int c = 0; c < 32; c++) {
        int idx = (b * 32 + c) * 256 + tid;
        outCur[idx] = outPrev[idx] + e[c];
    }
}

extern "C" void kernel_launch(void* const* d_in, const int* in_sizes, int n_in,
                              void* d_out, int out_size) {
    const float* z = (const float*)d_in[0];
    const float* w = (const float*)d_in[1];
    float* out = (float*)d_out;

    // L0 + L1 fully fused (each: dist + argmin + upsample + next-level prep)
    k_lvl0<<<64, 256>>>(z, w, out);
    k_lvl1<<<64, 256>>>(w, out, out + (size_t)NPIX);

    // L2: 1024 tokens
    k_dist<<<dim3(16, 16), 256>>>(w, 256, 2, OFF2);
    k_up<4, 8><<<64, 256>>>(w, out + (size_t)NPIX, out + 2 * (size_t)NPIX, 16, OFF3);

    // L3: 4096 tokens
    k_dist<<<dim3(64, 4), 256>>>(w, 1024, 8, OFF3);
    k_up<8, 16><<<64, 256>>>(w, out + 2 * (size_t)NPIX, out + 3 * (size_t)NPIX, 4, OFF4);

    // L4: 16384 tokens
    k_dist<<<dim3(256, 2), 256>>>(w, 2048, 16, OFF4);
    k_up_last<<<64, 256>>>(w, out + 3 * (size_t)NPIX, out + 4 * (size_t)NPIX, 2);
}